// round 2
// baseline (speedup 1.0000x reference)
#include <cuda_runtime.h>

#define N_TOTAL 16384
#define T       1024
#define VPT     (N_TOTAL / T)        // 16 elements per thread
#define NWARP   (T / 32)             // 32 warps

__global__ __launch_bounds__(T, 1)
void nll_single(const float4* __restrict__ pred4,
                const float4* __restrict__ label4,
                float* __restrict__ out, int out_size) {
    const int t    = threadIdx.x;
    const unsigned lane = t & 31u;
    const unsigned wid  = t >> 5;

    __shared__ float s_wtot[NWARP];
    __shared__ float s_rs[NWARP];
    __shared__ float s_rc[NWARP];

    // ---------------- Phase 1: load pred chunk, exp, local inclusive scan ----
    // Thread t owns elements [t*16, t*16+16) = float4 indices [t*4, t*4+4).
    float p[VPT];
    float r[VPT];   // running (inclusive) sums of exp within the chunk
    {
        float run = 0.f;
        #pragma unroll
        for (int g = 0; g < 4; g++) {
            float4 v = pred4[t * 4 + g];
            p[g * 4 + 0] = v.x; p[g * 4 + 1] = v.y;
            p[g * 4 + 2] = v.z; p[g * 4 + 3] = v.w;
        }
        #pragma unroll
        for (int k = 0; k < VPT; k++) {
            run += expf(p[k]);
            r[k] = run;
        }
    }

    // ---------------- Phase 1.5: issue label loads early (hide behind scan) --
    // label is (N,2) float pairs; thread's 16 pairs = 8 float4s at [t*8, t*8+8).
    unsigned mask = 0u;
    float cnt = 0.f;
    {
        #pragma unroll
        for (int g = 0; g < 8; g++) {
            float4 lv = label4[t * 8 + g];
            if (lv.y != 0.f) { mask |= 1u << (2 * g);     cnt += lv.y; }
            if (lv.w != 0.f) { mask |= 1u << (2 * g + 1); cnt += lv.w; }
        }
    }

    // ---------------- Phase 2: block-wide exclusive prefix of thread totals --
    const float tot = r[VPT - 1];
    float ws = tot;
    #pragma unroll
    for (int o = 1; o < 32; o <<= 1) {
        float n = __shfl_up_sync(0xffffffffu, ws, o);
        if (lane >= (unsigned)o) ws += n;
    }
    if (lane == 31) s_wtot[wid] = ws;
    __syncthreads();
    if (wid == 0) {
        float w = s_wtot[lane];
        #pragma unroll
        for (int o = 1; o < NWARP; o <<= 1) {
            float n = __shfl_up_sync(0xffffffffu, w, o);
            if (lane >= (unsigned)o) w += n;
        }
        s_wtot[lane] = w;
    }
    __syncthreads();
    const float P = (wid ? s_wtot[wid - 1] : 0.f) + (ws - tot); // exclusive prefix

    // ---------------- Phase 3: masked contributions -------------------------
    float c = 0.f;
    #pragma unroll
    for (int k = 0; k < VPT; k++) {
        if (mask & (1u << k)) {
            c += p[k] - logf(P + r[k]);
        }
    }

    // ---------------- Phase 4: block reduce (c, cnt) and write --------------
    #pragma unroll
    for (int o = 16; o > 0; o >>= 1) {
        c   += __shfl_down_sync(0xffffffffu, c, o);
        cnt += __shfl_down_sync(0xffffffffu, cnt, o);
    }
    if (lane == 0) { s_rs[wid] = c; s_rc[wid] = cnt; }
    __syncthreads();
    if (wid == 0) {
        float cs = (lane < NWARP) ? s_rs[lane] : 0.f;
        float ys = (lane < NWARP) ? s_rc[lane] : 0.f;
        #pragma unroll
        for (int o = 16; o > 0; o >>= 1) {
            cs += __shfl_down_sync(0xffffffffu, cs, o);
            ys += __shfl_down_sync(0xffffffffu, ys, o);
        }
        if (lane == 0) {
            float cost = (ys == 0.f) ? 0.f : -(cs / fmaxf(ys, 1.f));
            out[0] = cost;
            if (out_size > 1) out[1] = ys;
        }
    }
}

extern "C" void kernel_launch(void* const* d_in, const int* in_sizes, int n_in,
                              void* d_out, int out_size) {
    const float4* pred4  = (const float4*)d_in[0];
    const float4* label4 = (const float4*)d_in[1];
    float* out = (float*)d_out;

    nll_single<<<1, T>>>(pred4, label4, out, out_size);
}

// round 3
// speedup vs baseline: 2.5507x; 2.5507x over previous
#include <cuda_runtime.h>
#include <cstdint>

#define NC     8                 // cluster size (CTAs)
#define T      1024              // threads per CTA
#define NWARP  (T / 32)          // 32 warps
#define VPT    2                 // elements per thread (8*1024*2 = 16384)

__device__ __forceinline__ uint32_t ctarank() {
    uint32_t r; asm("mov.u32 %0, %%cluster_ctarank;" : "=r"(r)); return r;
}
__device__ __forceinline__ void st_cluster_f32(void* local_ptr, uint32_t target_rank, float v) {
    uint32_t a = (uint32_t)__cvta_generic_to_shared(local_ptr);
    uint32_t remote;
    asm("mapa.shared::cluster.u32 %0, %1, %2;" : "=r"(remote) : "r"(a), "r"(target_rank));
    asm volatile("st.shared::cluster.f32 [%0], %1;" :: "r"(remote), "f"(v) : "memory");
}
__device__ __forceinline__ void cluster_sync_() {
    asm volatile("barrier.cluster.arrive.aligned;" ::: "memory");
    asm volatile("barrier.cluster.wait.aligned;"   ::: "memory");
}

__global__ __launch_bounds__(T, 1) __cluster_dims__(NC, 1, 1)
void nll_cluster(const float2* __restrict__ pred2,
                 const float4* __restrict__ label4,
                 float* __restrict__ out, int out_size) {
    const int t = threadIdx.x;
    const unsigned lane = t & 31u;
    const unsigned wid  = t >> 5;
    const uint32_t rank = ctarank();

    __shared__ float s_warp[NWARP];     // warp scan totals
    __shared__ float s_ctatot[NC];      // peer CTA totals (written by peers)
    __shared__ float s_redc[NC];        // final reduce: contributions (CTA0 only used)
    __shared__ float s_redn[NC];        // final reduce: counts

    // ---------------- loads (issued up front, independent) ------------------
    const int g = rank * T + t;         // global thread index, owns elems 2g, 2g+1
    float2 pv = pred2[g];
    float4 lv = label4[g];              // (time0, ev0, time1, ev1)

    // ---------------- exp + local inclusive ---------------------------------
    float e0 = expf(pv.x);
    float e1 = expf(pv.y);
    float r0 = e0;
    float r1 = e0 + e1;
    float tot = r1;

    // ---------------- CTA-wide exclusive prefix of thread totals ------------
    float ws = tot;
    #pragma unroll
    for (int o = 1; o < 32; o <<= 1) {
        float n = __shfl_up_sync(0xffffffffu, ws, o);
        if (lane >= (unsigned)o) ws += n;
    }
    if (lane == 31) s_warp[wid] = ws;
    __syncthreads();
    if (wid == 0) {
        float w = s_warp[lane];
        #pragma unroll
        for (int o = 1; o < NWARP; o <<= 1) {
            float n = __shfl_up_sync(0xffffffffu, w, o);
            if (lane >= (unsigned)o) w += n;
        }
        s_warp[lane] = w;
    }
    __syncthreads();
    const float P = (wid ? s_warp[wid - 1] : 0.f) + (ws - tot); // excl prefix in CTA
    const float ctaTotal = s_warp[NWARP - 1];

    // ---------------- exchange CTA totals across cluster --------------------
    // thread i (i<NC) delivers my total into slot[my_rank] of CTA i's array.
    if (t < NC) st_cluster_f32(&s_ctatot[rank], (uint32_t)t, ctaTotal);
    cluster_sync_();

    float ctaExcl = 0.f;
    #pragma unroll
    for (int j = 0; j < NC; j++)
        if ((unsigned)j < rank) ctaExcl += s_ctatot[j];

    // ---------------- masked contributions ----------------------------------
    const float base = ctaExcl + P;
    float c = 0.f, cnt = 0.f;
    if (lv.y != 0.f) { c += lv.y * (pv.x - logf(base + r0)); cnt += lv.y; }
    if (lv.w != 0.f) { c += lv.w * (pv.y - logf(base + r1)); cnt += lv.w; }

    // ---------------- CTA reduce (c, cnt) -----------------------------------
    #pragma unroll
    for (int o = 16; o > 0; o >>= 1) {
        c   += __shfl_down_sync(0xffffffffu, c, o);
        cnt += __shfl_down_sync(0xffffffffu, cnt, o);
    }
    __shared__ float s_rs[NWARP], s_rc[NWARP];
    if (lane == 0) { s_rs[wid] = c; s_rc[wid] = cnt; }
    __syncthreads();
    if (t == 0) {
        float bc = 0.f, bn = 0.f;
        #pragma unroll
        for (int w = 0; w < NWARP; w++) { bc += s_rs[w]; bn += s_rc[w]; }
        // deliver to CTA 0's slots
        st_cluster_f32(&s_redc[rank], 0u, bc);
        st_cluster_f32(&s_redn[rank], 0u, bn);
    }
    cluster_sync_();

    if (rank == 0 && t == 0) {
        float cs = 0.f, ys = 0.f;
        #pragma unroll
        for (int j = 0; j < NC; j++) { cs += s_redc[j]; ys += s_redn[j]; }
        float cost = (ys == 0.f) ? 0.f : -(cs / fmaxf(ys, 1.f));
        out[0] = cost;
        if (out_size > 1) out[1] = ys;
    }
}

extern "C" void kernel_launch(void* const* d_in, const int* in_sizes, int n_in,
                              void* d_out, int out_size) {
    const float2* pred2  = (const float2*)d_in[0];
    const float4* label4 = (const float4*)d_in[1];
    float* out = (float*)d_out;

    nll_cluster<<<NC, T>>>(pred2, label4, out, out_size);
}